// round 16
// baseline (speedup 1.0000x reference)
#include <cuda_runtime.h>
#include <cuda_bf16.h>
#include <math.h>
#include <stdint.h>

#define N 1024
#define BATCH 32
#define NMAT 33          // 32 batch Laplacians + L0
#define EPSF 1e-7f
#define NSINK 40
#define NSTREAMS 9       // 8 batch-groups + 1 for L0
#define NBLK 4           // persistent blocks per matrix (33*4=132 <= 148 SMs)

// ---------------- static device scratch ------------------------------------
static __device__ float g_V[N * 4];
static __device__ float g_Ws[(size_t)N * N];
static __device__ float g_PrInv[BATCH * N];
static __device__ float g_part[(size_t)BATCH * N * 32];   // WP row-sum partials
static __device__ float g_LU[(size_t)NMAT * N * N];
static __device__ float g_ldp[NMAT * 16];                 // per-panel logdet partials
static __device__ float g_y[BATCH];
static __device__ int   g_bar[NMAT * 32];                 // matrix-local barriers
// bf16 split scratch (A: [abs row][64] k-contig; B: [abs col][64] k-contig)
static __device__ __nv_bfloat16 g_Ahi[(size_t)NMAT * N * 64];
static __device__ __nv_bfloat16 g_Alo[(size_t)NMAT * N * 64];
static __device__ __nv_bfloat16 g_Bhi[(size_t)NMAT * N * 64];
static __device__ __nv_bfloat16 g_Blo[(size_t)NMAT * N * 64];

// ---------------- host-side streams/events (created at load time) ----------
static cudaStream_t g_str[NSTREAMS];
static cudaEvent_t  g_evFin, g_evWs;
static cudaEvent_t  g_evJoin[NSTREAMS];
namespace {
struct StreamInit {
    StreamInit() {
        for (int i = 0; i < NSTREAMS; i++)
            cudaStreamCreateWithFlags(&g_str[i], cudaStreamNonBlocking);
        cudaEventCreateWithFlags(&g_evFin, cudaEventDisableTiming);
        cudaEventCreateWithFlags(&g_evWs, cudaEventDisableTiming);
        for (int i = 0; i < NSTREAMS; i++)
            cudaEventCreateWithFlags(&g_evJoin[i], cudaEventDisableTiming);
    }
};
static StreamInit s_streamInit;
}

// ---------------- warp-mma helpers (generic PTX, sm_80+) --------------------
__device__ __forceinline__ uint32_t smem_to_u32(const void* p) {
    uint32_t a;
    asm("{ .reg .u64 t; cvta.to.shared.u64 t, %1; cvt.u32.u64 %0, t; }"
        : "=r"(a) : "l"(p));
    return a;
}
__device__ __forceinline__ void ldsm_x4(uint32_t* r, uint32_t addr) {
    asm volatile("ldmatrix.sync.aligned.m8n8.x4.shared.b16 {%0,%1,%2,%3}, [%4];"
        : "=r"(r[0]), "=r"(r[1]), "=r"(r[2]), "=r"(r[3]) : "r"(addr));
}
__device__ __forceinline__ void mma16816(float* d, const uint32_t* a, const uint32_t* b) {
    asm volatile(
        "mma.sync.aligned.m16n8k16.row.col.f32.bf16.bf16.f32 "
        "{%0,%1,%2,%3}, {%4,%5,%6,%7}, {%8,%9}, {%0,%1,%2,%3};"
        : "+f"(d[0]), "+f"(d[1]), "+f"(d[2]), "+f"(d[3])
        : "r"(a[0]), "r"(a[1]), "r"(a[2]), "r"(a[3]), "r"(b[0]), "r"(b[1]));
}

// matrix-scoped inter-block barrier (CG grid.sync pattern; counters
// re-zeroed each run by k_zero so graph replays are correct)
__device__ __forceinline__ void mat_barrier(int* ctr) {
    __threadfence();
    __syncthreads();
    if (threadIdx.x == 0) {
        atomicAdd(ctr, 1);
        while (*((volatile int*)ctr) < NBLK) __nanosleep(64);
    }
    __syncthreads();
    __threadfence();
}

// ---------------- rank-4 micro-panel factorization (in-smem, 48 barriers) ---
__device__ __forceinline__ void panel_fact_r4(float* sU, int tid) {
    int lane = tid & 31;
    int warp = tid >> 5;
    int cc = tid & 63;
    int rg = tid >> 6;
    int r0 = lane, r1 = lane + 32;

    #pragma unroll 1
    for (int m = 0; m < 16; m++) {
        int c0 = m * 4;
        if (warp == 0) {
            float s0[4], s1[4];
            #pragma unroll
            for (int j = 0; j < 4; j++) {
                s0[j] = sU[r0 * 65 + c0 + j];
                s1[j] = sU[r1 * 65 + c0 + j];
            }
            #pragma unroll
            for (int j = 0; j < 4; j++) {
                int c = c0 + j;
                float u[4];
                #pragma unroll
                for (int jj = 0; jj < 4; jj++) {
                    float v = (c < 32) ? s0[jj] : s1[jj];
                    u[jj] = __shfl_sync(0xffffffffu, v, c & 31);
                }
                float inv = 1.0f / u[j];
                if (r0 > c) {
                    float l0 = s0[j] * inv;
                    s0[j] = l0;
                    #pragma unroll
                    for (int jj = 0; jj < 4; jj++)
                        if (jj > j) s0[jj] -= l0 * u[jj];
                }
                if (r1 > c) {
                    float l1 = s1[j] * inv;
                    s1[j] = l1;
                    #pragma unroll
                    for (int jj = 0; jj < 4; jj++)
                        if (jj > j) s1[jj] -= l1 * u[jj];
                }
            }
            #pragma unroll
            for (int j = 0; j < 4; j++) {
                sU[r0 * 65 + c0 + j] = s0[j];
                sU[r1 * 65 + c0 + j] = s1[j];
            }
        }
        __syncthreads();
        float u0 = 0.f, u1 = 0.f, u2 = 0.f, u3 = 0.f;
        bool act = (m < 15) && (cc > c0 + 3);
        if (act) {
            u0 = sU[(c0 + 0) * 65 + cc];
            u1 = sU[(c0 + 1) * 65 + cc];
            u2 = sU[(c0 + 2) * 65 + cc];
            u3 = sU[(c0 + 3) * 65 + cc];
            float l10 = sU[(c0 + 1) * 65 + c0];
            float l20 = sU[(c0 + 2) * 65 + c0];
            float l21 = sU[(c0 + 2) * 65 + c0 + 1];
            float l30 = sU[(c0 + 3) * 65 + c0];
            float l31 = sU[(c0 + 3) * 65 + c0 + 1];
            float l32 = sU[(c0 + 3) * 65 + c0 + 2];
            u1 -= l10 * u0;
            u2 -= l20 * u0 + l21 * u1;
            u3 -= l30 * u0 + l31 * u1 + l32 * u2;
            #pragma unroll 1
            for (int r = c0 + 4 + rg; r < 64; r += 4) {
                float acc = sU[r * 65 + cc];
                acc -= sU[r * 65 + c0 + 0] * u0 + sU[r * 65 + c0 + 1] * u1
                     + sU[r * 65 + c0 + 2] * u2 + sU[r * 65 + c0 + 3] * u3;
                sU[r * 65 + cc] = acc;
            }
        }
        __syncthreads();
        if (act && rg == 0) {
            sU[(c0 + 0) * 65 + cc] = u0;
            sU[(c0 + 1) * 65 + cc] = u1;
            sU[(c0 + 2) * 65 + cc] = u2;
            sU[(c0 + 3) * 65 + cc] = u3;
        }
        __syncthreads();
    }
}

// ---------------- prep kernels ----------------------------------------------

__global__ void k_zero() {
    int i = blockIdx.x * 256 + threadIdx.x;
    if (i < NMAT * 32) g_bar[i] = 0;
}

__global__ void k_vsoftmax(const float* __restrict__ Vc) {
    int i = blockIdx.x * 256 + threadIdx.x;
    if (i >= N) return;
    float4 v = reinterpret_cast<const float4*>(Vc)[i];
    float m = fmaxf(fmaxf(v.x, v.y), fmaxf(v.z, v.w));
    float a = __expf(v.x - m), b = __expf(v.y - m), c = __expf(v.z - m), d = __expf(v.w - m);
    float r = 1.0f / (a + b + c + d);
    float4 o; o.x = a * r; o.y = b * r; o.z = c * r; o.w = d * r;
    reinterpret_cast<float4*>(g_V)[i] = o;
}

__global__ void k_pr(const int* __restrict__ x) {
    int b = blockIdx.x;
    int i = threadIdx.x;
    int xi = x[b * N + i];
    float pr = g_V[i * 4 + xi];
    g_PrInv[b * N + i] = 1.0f / pr;
    __shared__ float sm[N];
    sm[i] = logf(pr + 1e-7f);
    __syncthreads();
    for (int st = 512; st > 0; st >>= 1) {
        if (i < st) sm[i] += sm[i + st];
        __syncthreads();
    }
    if (i == 0) g_y[b] = sm[0];
}

__global__ void k_ws(const float* __restrict__ W) {
    int i = blockIdx.x;
    __shared__ float sWs[N];
    __shared__ float sm[256];
    float s = 0.0f;
    for (int j = threadIdx.x; j < N; j += 256) {
        float v;
        if (i == j) v = 0.0f;
        else {
            float w = (i > j) ? W[(size_t)i * N + j] : W[(size_t)j * N + i];
            v = 1.0f / (1.0f + __expf(-w));
        }
        g_Ws[(size_t)i * N + j] = v;
        sWs[j] = v;
        s += v;
    }
    sm[threadIdx.x] = s;
    __syncthreads();
    for (int st = 128; st > 0; st >>= 1) {
        if (threadIdx.x < st) sm[threadIdx.x] += sm[threadIdx.x + st];
        __syncthreads();
    }
    float rowsum = sm[0];
    float* L0 = g_LU + (size_t)32 * N * N;
    if (i >= 1) {
        int p = i - 1;
        for (int q = threadIdx.x; q < N; q += 256) {
            float v;
            if (q == 1023) v = 0.0f;
            else v = ((q == p) ? rowsum : 0.0f) - sWs[q + 1] + 1e-7f;
            L0[(size_t)p * N + q] = v;
        }
    } else {
        for (int q = threadIdx.x; q < N; q += 256)
            L0[(size_t)1023 * N + q] = (q == 1023) ? 1.0f : 0.0f;
    }
}

// ---------------- Sinkhorn + scatter + fused row-sum partials ---------------
__global__ void k_sink(const int* __restrict__ x, const float* __restrict__ Ec) {
    int tid = threadIdx.x;
    int j = blockIdx.x * 128 + tid;
    int i = blockIdx.y + 1;

    __shared__ float se[128 * 17];
    __shared__ int   sxi[BATCH];
    __shared__ float spi[BATCH];
    if (tid < BATCH) {
        sxi[tid] = x[tid * N + i];
        spi[tid] = g_PrInv[tid * N + i];
    }

    float e[16];
    if (i != j) {
        const float4* p = reinterpret_cast<const float4*>(Ec) + (size_t)(i * N + j) * 4;
        float4 q0 = p[0], q1 = p[1], q2 = p[2], q3 = p[3];
        e[0] = __expf(q0.x); e[1] = __expf(q0.y); e[2] = __expf(q0.z); e[3] = __expf(q0.w);
        e[4] = __expf(q1.x); e[5] = __expf(q1.y); e[6] = __expf(q1.z); e[7] = __expf(q1.w);
        e[8] = __expf(q2.x); e[9] = __expf(q2.y); e[10] = __expf(q2.z); e[11] = __expf(q2.w);
        e[12] = __expf(q3.x); e[13] = __expf(q3.y); e[14] = __expf(q3.z); e[15] = __expf(q3.w);
        float s = 0.0f;
        #pragma unroll
        for (int t = 0; t < 16; t++) s += e[t];
        float r0 = __fdividef(1.0f, s);
        #pragma unroll
        for (int t = 0; t < 16; t++) e[t] *= r0;

        float4 vi4 = reinterpret_cast<const float4*>(g_V)[i];
        float4 vj4 = reinterpret_cast<const float4*>(g_V)[j];
        float Vi[4] = {vi4.x, vi4.y, vi4.z, vi4.w};
        float Vj[4] = {vj4.x, vj4.y, vj4.z, vj4.w};

        #pragma unroll 1
        for (int it = 0; it < NSINK; ++it) {
            #pragma unroll
            for (int a = 0; a < 4; a++) {
                float rs = e[4*a] + e[4*a+1] + e[4*a+2] + e[4*a+3];
                float rr = __fdividef(Vi[a], rs + EPSF);
                e[4*a] *= rr; e[4*a+1] *= rr; e[4*a+2] *= rr; e[4*a+3] *= rr;
            }
            #pragma unroll
            for (int b = 0; b < 4; b++) {
                float cs = e[b] + e[b+4] + e[b+8] + e[b+12];
                float cc = __fdividef(Vj[b], cs + EPSF);
                e[b] *= cc; e[b+4] *= cc; e[b+8] *= cc; e[b+12] *= cc;
            }
        }
        float t = 0.0f;
        #pragma unroll
        for (int u = 0; u < 16; u++) t += e[u];
        float tr = __fdividef(1.0f, t + EPSF);
        #pragma unroll
        for (int u = 0; u < 16; u++)
            e[u] = fminf(fmaxf(e[u] * tr, 0.0f), 1.0f);
    } else {
        #pragma unroll
        for (int t = 0; t < 16; t++) e[t] = 0.0f;
    }

    #pragma unroll
    for (int t = 0; t < 16; t++) se[tid * 17 + t] = e[t];
    __syncthreads();

    float wij = g_Ws[(size_t)i * N + j];
    int pidx = blockIdx.x * 4 + (tid >> 5);
    #pragma unroll 1
    for (int b = 0; b < BATCH; b++) {
        int a = sxi[b];
        int c = x[b * N + j];
        float val = wij * se[tid * 17 + (a * 4 + c)] * spi[b] * g_PrInv[b * N + j];
        if (j != 0)
            g_LU[(size_t)b * N * N + (size_t)(i - 1) * N + (j - 1)] = 1e-7f - val;
        float ws = val;
        #pragma unroll
        for (int o = 16; o > 0; o >>= 1)
            ws += __shfl_down_sync(0xffffffffu, ws, o);
        if ((tid & 31) == 0)
            g_part[((size_t)b * N + i) * 32 + pidx] = ws;
    }
}

// finalize: diag from partials, pad col/row. One block per batch matrix.
__global__ void k_fin() {
    int b = blockIdx.x;
    float* C = g_LU + (size_t)b * N * N;
    for (int p = threadIdx.x; p < 1023; p += 256) {
        const float* pp = g_part + ((size_t)b * N + (p + 1)) * 32;
        float s = 0.0f;
        #pragma unroll
        for (int q = 0; q < 32; q++) s += pp[q];
        C[(size_t)p * N + p] = s + 1e-7f;
        C[(size_t)p * N + 1023] = 0.0f;
    }
    for (int q = threadIdx.x; q < N; q += 256)
        C[(size_t)1023 * N + q] = (q == 1023) ? 1.0f : 0.0f;
}

// ---------------- persistent LU: whole chain in ONE kernel -------------------
#define SROW 72
#define SM_A_HI 0
#define SM_A_LO (128 * SROW * 2)
#define SM_B_HI (2 * 128 * SROW * 2)
#define SM_B_LO (3 * 128 * SROW * 2)
#define SM_MMA_BYTES (4 * 128 * SROW * 2)
#define SM_U    SM_MMA_BYTES                       // float[64*65]
#define SM_INV  (SM_U + 16640)                     // float[64]
#define SM_RED  (SM_INV + 256)                     // float[64]
#define SM_LU_BYTES (SM_RED + 256)                 // ~91 KB

// HMMA tile update: C[row0..+127][col0..+127] -= L21*U12 (K=64)
__device__ __forceinline__ void gemm_tile(char* smc, uint32_t sb, float* M,
                                          size_t mo, int row0, int col0) {
    int tid = threadIdx.x;
    int lane = tid & 31, wid = tid >> 5;
    __syncthreads();   // smem reuse fence (uniform call)
    {
        int r = tid >> 1;
        int h = (tid & 1) * 4;
        int ga = min(row0 + r, N - 1);
        int gb = min(col0 + r, N - 1);
        const uint4* pAhi = reinterpret_cast<const uint4*>(g_Ahi + mo + (size_t)ga * 64);
        const uint4* pAlo = reinterpret_cast<const uint4*>(g_Alo + mo + (size_t)ga * 64);
        const uint4* pBhi = reinterpret_cast<const uint4*>(g_Bhi + mo + (size_t)gb * 64);
        const uint4* pBlo = reinterpret_cast<const uint4*>(g_Blo + mo + (size_t)gb * 64);
        #pragma unroll
        for (int c = 0; c < 4; c++) {
            int chunk = h + c;
            size_t so = (size_t)r * SROW * 2 + chunk * 16;
            *reinterpret_cast<uint4*>(smc + SM_A_HI + so) = pAhi[chunk];
            *reinterpret_cast<uint4*>(smc + SM_A_LO + so) = pAlo[chunk];
            *reinterpret_cast<uint4*>(smc + SM_B_HI + so) = pBhi[chunk];
            *reinterpret_cast<uint4*>(smc + SM_B_LO + so) = pBlo[chunk];
        }
    }
    __syncthreads();

    int wm = (wid & 3) * 32;
    int wn = (wid >> 2) * 64;

    float acc[2][8][4];
    #pragma unroll
    for (int mi = 0; mi < 2; mi++)
        #pragma unroll
        for (int ni = 0; ni < 8; ni++)
            #pragma unroll
            for (int q = 0; q < 4; q++) acc[mi][ni][q] = 0.0f;

    uint32_t aBase = sb + SM_A_HI +
        (uint32_t)(((wm + (lane & 15)) * SROW + (lane >> 4) * 8) * 2);
    uint32_t bBase = sb + SM_B_HI +
        (uint32_t)(((wn + (lane >> 4) * 8 + (lane & 7)) * SROW + ((lane >> 3) & 1) * 8) * 2);
    const uint32_t LO = (uint32_t)(128 * SROW * 2);

    #pragma unroll
    for (int ks = 0; ks < 4; ks++) {
        uint32_t ko = ks * 16 * 2;
        uint32_t a_hi[2][4], a_lo[2][4];
        uint32_t b_hi[4][4], b_lo[4][4];
        #pragma unroll
        for (int mi = 0; mi < 2; mi++) {
            uint32_t ad = aBase + (uint32_t)(mi * 16 * SROW * 2) + ko;
            ldsm_x4(a_hi[mi], ad);
            ldsm_x4(a_lo[mi], ad + LO);
        }
        #pragma unroll
        for (int np = 0; np < 4; np++) {
            uint32_t bd = bBase + (uint32_t)(np * 16 * SROW * 2) + ko;
            ldsm_x4(b_hi[np], bd);
            ldsm_x4(b_lo[np], bd + LO);
        }
        #pragma unroll
        for (int mi = 0; mi < 2; mi++) {
            #pragma unroll
            for (int ni = 0; ni < 8; ni++) {
                const uint32_t* bh = &b_hi[ni >> 1][(ni & 1) * 2];
                const uint32_t* bl = &b_lo[ni >> 1][(ni & 1) * 2];
                mma16816(acc[mi][ni], a_hi[mi], bh);
                mma16816(acc[mi][ni], a_hi[mi], bl);
                mma16816(acc[mi][ni], a_lo[mi], bh);
            }
        }
    }

    int cr = lane >> 2;
    int cc2 = (lane & 3) * 2;
    #pragma unroll
    for (int mi = 0; mi < 2; mi++) {
        #pragma unroll
        for (int ni = 0; ni < 8; ni++) {
            int cc = col0 + wn + ni * 8 + cc2;
            if (cc < N) {
                int r0 = row0 + wm + mi * 16 + cr;
                if (r0 < N) {
                    float2* p = reinterpret_cast<float2*>(&M[(size_t)r0 * N + cc]);
                    float2 v = *p;
                    v.x -= acc[mi][ni][0]; v.y -= acc[mi][ni][1];
                    *p = v;
                }
                int r1 = row0 + wm + mi * 16 + cr + 8;
                if (r1 < N) {
                    float2* p = reinterpret_cast<float2*>(&M[(size_t)r1 * N + cc]);
                    float2 v = *p;
                    v.x -= acc[mi][ni][2]; v.y -= acc[mi][ni][3];
                    *p = v;
                }
            }
        }
    }
}

__global__ void __launch_bounds__(256) k_lu(int matBase) {
    extern __shared__ __align__(16) char smc[];
    uint32_t sb = smem_to_u32(smc);
    float* sU   = reinterpret_cast<float*>(smc + SM_U);
    float* sInv = reinterpret_cast<float*>(smc + SM_INV);
    float* sRed = reinterpret_cast<float*>(smc + SM_RED);
    int mat = matBase + blockIdx.y;
    int bx = blockIdx.x;
    float* A = g_LU + (size_t)mat * N * N;
    int* bar = g_bar + mat * 32;
    int tid = threadIdx.x;
    size_t mo = (size_t)mat * N * 64;

    #pragma unroll 1
    for (int s = 0; s < 15; s++) {
        int k = s * 64;
        int m2 = N - k - 64;

        // phase A: panel factorization (redundant per block, parallel)
        for (int t = tid; t < 64 * 64; t += 256) {
            int r = t >> 6, c = t & 63;
            sU[r * 65 + c] = A[(size_t)(k + r) * N + k + c];
        }
        __syncthreads();
        panel_fact_r4(sU, tid);
        if (tid < 64) {
            float d = sU[tid * 65 + tid];
            sInv[tid] = 1.0f / d;
            sRed[tid] = logf(fabsf(d));
        }
        __syncthreads();
        if (bx == 0 && tid == 0) {
            float sum = 0.0f;
            #pragma unroll
            for (int u = 0; u < 64; u++) sum += sRed[u];
            g_ldp[mat * 16 + s] = sum;
        }

        // phase A2: TRSM units (u<nrow: L21 row chunks; else U12 col chunks)
        int nrow = (m2 + 255) >> 8;
        #pragma unroll 1
        for (int u = bx; u < 2 * nrow; u += NBLK) {
            int isCol = (u >= nrow);
            int g = k + 64 + (isCol ? (u - nrow) : u) * 256 + tid;
            if (g < N) {
                size_t so = mo + (size_t)g * 64;
                float a[64];
                if (!isCol) {
                    const float* rowp = A + (size_t)g * N + k;
                    #pragma unroll
                    for (int c = 0; c < 16; c++) {
                        float4 v = reinterpret_cast<const float4*>(rowp)[c];
                        a[4 * c] = v.x; a[4 * c + 1] = v.y;
                        a[4 * c + 2] = v.z; a[4 * c + 3] = v.w;
                    }
                    #pragma unroll
                    for (int d = 0; d < 64; d++) {
                        a[d] *= sInv[d];
                        #pragma unroll
                        for (int c = d + 1; c < 64; c++) a[c] -= a[d] * sU[d * 65 + c];
                    }
                    #pragma unroll
                    for (int c8 = 0; c8 < 8; c8++) {
                        union { uint4 u4; __nv_bfloat16 h[8]; } ph, pl;
                        #pragma unroll
                        for (int q = 0; q < 8; q++) {
                            float v = a[c8 * 8 + q];
                            ph.h[q] = __float2bfloat16(v);
                            pl.h[q] = __float2bfloat16(v - __bfloat162float(ph.h[q]));
                        }
                        reinterpret_cast<uint4*>(g_Ahi + so)[c8] = ph.u4;
                        reinterpret_cast<uint4*>(g_Alo + so)[c8] = pl.u4;
                    }
                } else {
                    #pragma unroll
                    for (int d = 0; d < 64; d++) a[d] = A[(size_t)(k + d) * N + g];
                    #pragma unroll
                    for (int d = 0; d < 64; d++) {
                        #pragma unroll
                        for (int r = d + 1; r < 64; r++) a[r] -= sU[r * 65 + d] * a[d];
                    }
                    #pragma unroll
                    for (int c8 = 0; c8 < 8; c8++) {
                        union { uint4 u4; __nv_bfloat16 h[8]; } ph, pl;
                        #pragma unroll
                        for (int q = 0; q < 8; q++) {
                            float v = a[c8 * 8 + q];
                            ph.h[q] = __float2bfloat16(v);
                            pl.h[q] = __float2bfloat16(v - __bfloat162float(ph.h[q]));
                        }
                        reinterpret_cast<uint4*>(g_Bhi + so)[c8] = ph.u4;
                        reinterpret_cast<uint4*>(g_Blo + so)[c8] = pl.u4;
                    }
                }
            }
        }
        mat_barrier(bar + 2 * s);

        // phase B: trailing-update tiles, round-robin over NBLK blocks
        int gx = (m2 + 127) >> 7;
        int ntile = gx * gx;
        #pragma unroll 1
        for (int t = bx; t < ntile; t += NBLK) {
            int tby = t / gx;
            int tbx = t - tby * gx;
            gemm_tile(smc, sb, A, mo, k + 64 + tby * 128, k + 64 + tbx * 128);
        }
        mat_barrier(bar + 2 * s + 1);
    }

    // final 64x64 panel: logdet partial only (block 0)
    if (bx == 0) {
        const int k = 960;
        for (int t = tid; t < 64 * 64; t += 256) {
            int r = t >> 6, c = t & 63;
            sU[r * 65 + c] = A[(size_t)(k + r) * N + k + c];
        }
        __syncthreads();
        panel_fact_r4(sU, tid);
        if (tid < 64) sRed[tid] = logf(fabsf(sU[tid * 65 + tid]));
        __syncthreads();
        if (tid == 0) {
            float sum = 0.0f;
            #pragma unroll
            for (int u = 0; u < 64; u++) sum += sRed[u];
            g_ldp[mat * 16 + 15] = sum;
        }
    }
}

// ---------------- output ------------------------------------------------------

__global__ void k_out(float* __restrict__ out) {
    int b = threadIdx.x;    // 32 threads
    float s0 = 0.0f;
    #pragma unroll
    for (int t = 0; t < 16; t++) s0 += g_ldp[32 * 16 + t];
    if (b < BATCH) {
        float s = 0.0f;
        #pragma unroll
        for (int t = 0; t < 16; t++) s += g_ldp[b * 16 + t];
        out[b] = g_y[b] + s - s0;
    }
}

// ---------------- launch ------------------------------------------------------

extern "C" void kernel_launch(void* const* d_in, const int* in_sizes, int n_in,
                              void* d_out, int out_size) {
    const int*   x  = (const int*)d_in[0];
    const float* W  = (const float*)d_in[1];
    const float* Vc = (const float*)d_in[2];
    const float* Ec = (const float*)d_in[3];
    float* out = (float*)d_out;
    (void)in_sizes; (void)n_in; (void)out_size;

    cudaFuncSetAttribute(k_lu, cudaFuncAttributeMaxDynamicSharedMemorySize, SM_LU_BYTES);

    // prep on the default (capture) stream; barriers zeroed first, k_ws early
    k_zero<<<(NMAT * 32 + 255) / 256, 256>>>();
    k_ws<<<N, 256>>>(W);
    cudaEventRecord(g_evWs, 0);
    k_vsoftmax<<<4, 256>>>(Vc);
    k_pr<<<BATCH, 1024>>>(x);
    k_sink<<<dim3(8, N - 1), 128>>>(x, Ec);
    k_fin<<<BATCH, 256>>>();
    cudaEventRecord(g_evFin, 0);

    // L0 chain forks right after k_ws (overlaps the Sinkhorn)
    cudaStreamWaitEvent(g_str[8], g_evWs, 0);
    k_lu<<<dim3(NBLK, 1), 256, SM_LU_BYTES, g_str[8]>>>(32);
    cudaEventRecord(g_evJoin[8], g_str[8]);

    // 8 batch-matrix chains fork after k_fin (4 matrices per launch)
    for (int i = 0; i < 8; i++) {
        cudaStreamWaitEvent(g_str[i], g_evFin, 0);
        k_lu<<<dim3(NBLK, 4), 256, SM_LU_BYTES, g_str[i]>>>(i * 4);
        cudaEventRecord(g_evJoin[i], g_str[i]);
    }
    for (int i = 0; i < NSTREAMS; i++)
        cudaStreamWaitEvent(0, g_evJoin[i], 0);

    k_out<<<1, 32>>>(out);
}

// round 17
// speedup vs baseline: 2.2597x; 2.2597x over previous
#include <cuda_runtime.h>
#include <cuda_bf16.h>
#include <math.h>
#include <stdint.h>

#define N 1024
#define BATCH 32
#define NMAT 33          // 32 batch Laplacians + L0
#define EPSF 1e-7f
#define NSINK 40
#define NSTREAMS 9       // 8 batch-groups + 1 for L0

// ---------------- static device scratch ------------------------------------
static __device__ float g_V[N * 4];
static __device__ float g_Ws[(size_t)N * N];
static __device__ float g_PrInv[BATCH * N];
static __device__ float g_part[(size_t)BATCH * N * 32];   // WP row-sum partials
static __device__ float g_LU[(size_t)NMAT * N * N];
static __device__ float g_ldp[NMAT * 16];                 // per-panel logdet partials
static __device__ float g_y[BATCH];
static __device__ float g_panel[NMAT * 4224];             // factored panel (4160) + inv (64)
// bf16 split scratch (A: [abs row][64] k-contig; B: [abs col][64] k-contig)
static __device__ __nv_bfloat16 g_Ahi[(size_t)NMAT * N * 64];
static __device__ __nv_bfloat16 g_Alo[(size_t)NMAT * N * 64];
static __device__ __nv_bfloat16 g_Bhi[(size_t)NMAT * N * 64];
static __device__ __nv_bfloat16 g_Blo[(size_t)NMAT * N * 64];

// ---------------- host-side streams/events (created at load time) ----------
static cudaStream_t g_str[NSTREAMS];
static cudaEvent_t  g_evFin, g_evWs;
static cudaEvent_t  g_evJoin[NSTREAMS];
namespace {
struct StreamInit {
    StreamInit() {
        for (int i = 0; i < NSTREAMS; i++)
            cudaStreamCreateWithFlags(&g_str[i], cudaStreamNonBlocking);
        cudaEventCreateWithFlags(&g_evFin, cudaEventDisableTiming);
        cudaEventCreateWithFlags(&g_evWs, cudaEventDisableTiming);
        for (int i = 0; i < NSTREAMS; i++)
            cudaEventCreateWithFlags(&g_evJoin[i], cudaEventDisableTiming);
    }
};
static StreamInit s_streamInit;
}

// ---------------- warp-mma helpers (generic PTX, sm_80+) --------------------
__device__ __forceinline__ uint32_t smem_to_u32(const void* p) {
    uint32_t a;
    asm("{ .reg .u64 t; cvta.to.shared.u64 t, %1; cvt.u32.u64 %0, t; }"
        : "=r"(a) : "l"(p));
    return a;
}
__device__ __forceinline__ void ldsm_x4(uint32_t* r, uint32_t addr) {
    asm volatile("ldmatrix.sync.aligned.m8n8.x4.shared.b16 {%0,%1,%2,%3}, [%4];"
        : "=r"(r[0]), "=r"(r[1]), "=r"(r[2]), "=r"(r[3]) : "r"(addr));
}
__device__ __forceinline__ void mma16816(float* d, const uint32_t* a, const uint32_t* b) {
    asm volatile(
        "mma.sync.aligned.m16n8k16.row.col.f32.bf16.bf16.f32 "
        "{%0,%1,%2,%3}, {%4,%5,%6,%7}, {%8,%9}, {%0,%1,%2,%3};"
        : "+f"(d[0]), "+f"(d[1]), "+f"(d[2]), "+f"(d[3])
        : "r"(a[0]), "r"(a[1]), "r"(a[2]), "r"(a[3]), "r"(b[0]), "r"(b[1]));
}

// ---------------- rank-4 micro-panel factorization (in-smem) ----------------
__device__ __forceinline__ void panel_fact_r4(float* sU, int tid) {
    int lane = tid & 31;
    int warp = tid >> 5;
    int cc = tid & 63;
    int rg = tid >> 6;
    int r0 = lane, r1 = lane + 32;

    #pragma unroll 1
    for (int m = 0; m < 16; m++) {
        int c0 = m * 4;
        if (warp == 0) {
            float s0[4], s1[4];
            #pragma unroll
            for (int j = 0; j < 4; j++) {
                s0[j] = sU[r0 * 65 + c0 + j];
                s1[j] = sU[r1 * 65 + c0 + j];
            }
            #pragma unroll
            for (int j = 0; j < 4; j++) {
                int c = c0 + j;
                float u[4];
                #pragma unroll
                for (int jj = 0; jj < 4; jj++) {
                    float v = (c < 32) ? s0[jj] : s1[jj];
                    u[jj] = __shfl_sync(0xffffffffu, v, c & 31);
                }
                float inv = 1.0f / u[j];
                if (r0 > c) {
                    float l0 = s0[j] * inv;
                    s0[j] = l0;
                    #pragma unroll
                    for (int jj = 0; jj < 4; jj++)
                        if (jj > j) s0[jj] -= l0 * u[jj];
                }
                if (r1 > c) {
                    float l1 = s1[j] * inv;
                    s1[j] = l1;
                    #pragma unroll
                    for (int jj = 0; jj < 4; jj++)
                        if (jj > j) s1[jj] -= l1 * u[jj];
                }
            }
            #pragma unroll
            for (int j = 0; j < 4; j++) {
                sU[r0 * 65 + c0 + j] = s0[j];
                sU[r1 * 65 + c0 + j] = s1[j];
            }
        }
        __syncthreads();
        float u0 = 0.f, u1 = 0.f, u2 = 0.f, u3 = 0.f;
        bool act = (m < 15) && (cc > c0 + 3);
        if (act) {
            u0 = sU[(c0 + 0) * 65 + cc];
            u1 = sU[(c0 + 1) * 65 + cc];
            u2 = sU[(c0 + 2) * 65 + cc];
            u3 = sU[(c0 + 3) * 65 + cc];
            float l10 = sU[(c0 + 1) * 65 + c0];
            float l20 = sU[(c0 + 2) * 65 + c0];
            float l21 = sU[(c0 + 2) * 65 + c0 + 1];
            float l30 = sU[(c0 + 3) * 65 + c0];
            float l31 = sU[(c0 + 3) * 65 + c0 + 1];
            float l32 = sU[(c0 + 3) * 65 + c0 + 2];
            u1 -= l10 * u0;
            u2 -= l20 * u0 + l21 * u1;
            u3 -= l30 * u0 + l31 * u1 + l32 * u2;
            #pragma unroll 1
            for (int r = c0 + 4 + rg; r < 64; r += 4) {
                float acc = sU[r * 65 + cc];
                acc -= sU[r * 65 + c0 + 0] * u0 + sU[r * 65 + c0 + 1] * u1
                     + sU[r * 65 + c0 + 2] * u2 + sU[r * 65 + c0 + 3] * u3;
                sU[r * 65 + cc] = acc;
            }
        }
        __syncthreads();
        if (act && rg == 0) {
            sU[(c0 + 0) * 65 + cc] = u0;
            sU[(c0 + 1) * 65 + cc] = u1;
            sU[(c0 + 2) * 65 + cc] = u2;
            sU[(c0 + 3) * 65 + cc] = u3;
        }
        __syncthreads();
    }
}

// ---------------- prep kernels ----------------------------------------------

__global__ void k_vsoftmax(const float* __restrict__ Vc) {
    int i = blockIdx.x * 256 + threadIdx.x;
    if (i >= N) return;
    float4 v = reinterpret_cast<const float4*>(Vc)[i];
    float m = fmaxf(fmaxf(v.x, v.y), fmaxf(v.z, v.w));
    float a = __expf(v.x - m), b = __expf(v.y - m), c = __expf(v.z - m), d = __expf(v.w - m);
    float r = 1.0f / (a + b + c + d);
    float4 o; o.x = a * r; o.y = b * r; o.z = c * r; o.w = d * r;
    reinterpret_cast<float4*>(g_V)[i] = o;
}

__global__ void k_pr(const int* __restrict__ x) {
    int b = blockIdx.x;
    int i = threadIdx.x;
    int xi = x[b * N + i];
    float pr = g_V[i * 4 + xi];
    g_PrInv[b * N + i] = 1.0f / pr;
    __shared__ float sm[N];
    sm[i] = logf(pr + 1e-7f);
    __syncthreads();
    for (int st = 512; st > 0; st >>= 1) {
        if (i < st) sm[i] += sm[i + st];
        __syncthreads();
    }
    if (i == 0) g_y[b] = sm[0];
}

__global__ void k_ws(const float* __restrict__ W) {
    int i = blockIdx.x;
    __shared__ float sWs[N];
    __shared__ float sm[256];
    float s = 0.0f;
    for (int j = threadIdx.x; j < N; j += 256) {
        float v;
        if (i == j) v = 0.0f;
        else {
            float w = (i > j) ? W[(size_t)i * N + j] : W[(size_t)j * N + i];
            v = 1.0f / (1.0f + __expf(-w));
        }
        g_Ws[(size_t)i * N + j] = v;
        sWs[j] = v;
        s += v;
    }
    sm[threadIdx.x] = s;
    __syncthreads();
    for (int st = 128; st > 0; st >>= 1) {
        if (threadIdx.x < st) sm[threadIdx.x] += sm[threadIdx.x + st];
        __syncthreads();
    }
    float rowsum = sm[0];
    float* L0 = g_LU + (size_t)32 * N * N;
    if (i >= 1) {
        int p = i - 1;
        for (int q = threadIdx.x; q < N; q += 256) {
            float v;
            if (q == 1023) v = 0.0f;
            else v = ((q == p) ? rowsum : 0.0f) - sWs[q + 1] + 1e-7f;
            L0[(size_t)p * N + q] = v;
        }
    } else {
        for (int q = threadIdx.x; q < N; q += 256)
            L0[(size_t)1023 * N + q] = (q == 1023) ? 1.0f : 0.0f;
    }
}

// ---------------- Sinkhorn + scatter + fused row-sum partials ---------------
__global__ void k_sink(const int* __restrict__ x, const float* __restrict__ Ec) {
    int tid = threadIdx.x;
    int j = blockIdx.x * 128 + tid;
    int i = blockIdx.y + 1;

    __shared__ float se[128 * 17];
    __shared__ int   sxi[BATCH];
    __shared__ float spi[BATCH];
    if (tid < BATCH) {
        sxi[tid] = x[tid * N + i];
        spi[tid] = g_PrInv[tid * N + i];
    }

    float e[16];
    if (i != j) {
        const float4* p = reinterpret_cast<const float4*>(Ec) + (size_t)(i * N + j) * 4;
        float4 q0 = p[0], q1 = p[1], q2 = p[2], q3 = p[3];
        e[0] = __expf(q0.x); e[1] = __expf(q0.y); e[2] = __expf(q0.z); e[3] = __expf(q0.w);
        e[4] = __expf(q1.x); e[5] = __expf(q1.y); e[6] = __expf(q1.z); e[7] = __expf(q1.w);
        e[8] = __expf(q2.x); e[9] = __expf(q2.y); e[10] = __expf(q2.z); e[11] = __expf(q2.w);
        e[12] = __expf(q3.x); e[13] = __expf(q3.y); e[14] = __expf(q3.z); e[15] = __expf(q3.w);
        float s = 0.0f;
        #pragma unroll
        for (int t = 0; t < 16; t++) s += e[t];
        float r0 = __fdividef(1.0f, s);
        #pragma unroll
        for (int t = 0; t < 16; t++) e[t] *= r0;

        float4 vi4 = reinterpret_cast<const float4*>(g_V)[i];
        float4 vj4 = reinterpret_cast<const float4*>(g_V)[j];
        float Vi[4] = {vi4.x, vi4.y, vi4.z, vi4.w};
        float Vj[4] = {vj4.x, vj4.y, vj4.z, vj4.w};

        #pragma unroll 1
        for (int it = 0; it < NSINK; ++it) {
            #pragma unroll
            for (int a = 0; a < 4; a++) {
                float rs = e[4*a] + e[4*a+1] + e[4*a+2] + e[4*a+3];
                float rr = __fdividef(Vi[a], rs + EPSF);
                e[4*a] *= rr; e[4*a+1] *= rr; e[4*a+2] *= rr; e[4*a+3] *= rr;
            }
            #pragma unroll
            for (int b = 0; b < 4; b++) {
                float cs = e[b] + e[b+4] + e[b+8] + e[b+12];
                float cc = __fdividef(Vj[b], cs + EPSF);
                e[b] *= cc; e[b+4] *= cc; e[b+8] *= cc; e[b+12] *= cc;
            }
        }
        float t = 0.0f;
        #pragma unroll
        for (int u = 0; u < 16; u++) t += e[u];
        float tr = __fdividef(1.0f, t + EPSF);
        #pragma unroll
        for (int u = 0; u < 16; u++)
            e[u] = fminf(fmaxf(e[u] * tr, 0.0f), 1.0f);
    } else {
        #pragma unroll
        for (int t = 0; t < 16; t++) e[t] = 0.0f;
    }

    #pragma unroll
    for (int t = 0; t < 16; t++) se[tid * 17 + t] = e[t];
    __syncthreads();

    float wij = g_Ws[(size_t)i * N + j];
    int pidx = blockIdx.x * 4 + (tid >> 5);
    #pragma unroll 1
    for (int b = 0; b < BATCH; b++) {
        int a = sxi[b];
        int c = x[b * N + j];
        float val = wij * se[tid * 17 + (a * 4 + c)] * spi[b] * g_PrInv[b * N + j];
        if (j != 0)
            g_LU[(size_t)b * N * N + (size_t)(i - 1) * N + (j - 1)] = 1e-7f - val;
        float ws = val;
        #pragma unroll
        for (int o = 16; o > 0; o >>= 1)
            ws += __shfl_down_sync(0xffffffffu, ws, o);
        if ((tid & 31) == 0)
            g_part[((size_t)b * N + i) * 32 + pidx] = ws;
    }
}

// finalize: diag from partials, pad col/row. One block per batch matrix.
__global__ void k_fin() {
    int b = blockIdx.x;
    float* C = g_LU + (size_t)b * N * N;
    for (int p = threadIdx.x; p < 1023; p += 256) {
        const float* pp = g_part + ((size_t)b * N + (p + 1)) * 32;
        float s = 0.0f;
        #pragma unroll
        for (int q = 0; q < 32; q++) s += pp[q];
        C[(size_t)p * N + p] = s + 1e-7f;
        C[(size_t)p * N + 1023] = 0.0f;
    }
    for (int q = threadIdx.x; q < N; q += 256)
        C[(size_t)1023 * N + q] = (q == 1023) ? 1.0f : 0.0f;
}

// ---------------- TRSM + bf16 split (panel from g_panel unless fact) --------
// z==0 -> L21 rows -> g_Ahi/g_Alo; z==1 -> U12 cols -> g_Bhi/g_Blo.
__global__ void k_trsm(int k, int s, int matBase, int fact) {
    int mat = matBase + blockIdx.y;
    float* A = g_LU + (size_t)mat * N * N;
    int tid = threadIdx.x;
    __shared__ float sU[64 * 65];
    __shared__ float sInv[64];
    __shared__ float red[64];

    if (fact) {
        for (int t = tid; t < 64 * 64; t += 256) {
            int r = t >> 6, c = t & 63;
            sU[r * 65 + c] = A[(size_t)(k + r) * N + k + c];
        }
        __syncthreads();
        panel_fact_r4(sU, tid);
        if (tid < 64) {
            float d = sU[tid * 65 + tid];
            sInv[tid] = 1.0f / d;
            red[tid] = logf(fabsf(d));
        }
        __syncthreads();
        if (blockIdx.x == 0 && blockIdx.z == 0 && tid == 0) {
            float sum = 0.0f;
            #pragma unroll
            for (int u = 0; u < 64; u++) sum += red[u];
            g_ldp[mat * 16 + s] = sum;
        }
    } else {
        const float* P = g_panel + mat * 4224;
        for (int t = tid; t < 4160; t += 256) sU[t] = P[t];
        if (tid < 64) sInv[tid] = P[4160 + tid];
        __syncthreads();
    }

    int g = k + 64 + blockIdx.x * 256 + tid;
    if (g >= N) return;
    size_t so = (size_t)mat * N * 64 + (size_t)g * 64;
    float a[64];
    if (blockIdx.z == 0) {
        const float* rowp = A + (size_t)g * N + k;
        #pragma unroll
        for (int c = 0; c < 16; c++) {
            float4 v = reinterpret_cast<const float4*>(rowp)[c];
            a[4 * c] = v.x; a[4 * c + 1] = v.y; a[4 * c + 2] = v.z; a[4 * c + 3] = v.w;
        }
        #pragma unroll
        for (int d = 0; d < 64; d++) {
            a[d] *= sInv[d];
            #pragma unroll
            for (int c = d + 1; c < 64; c++) a[c] -= a[d] * sU[d * 65 + c];
        }
        #pragma unroll
        for (int c8 = 0; c8 < 8; c8++) {
            union { uint4 u4; __nv_bfloat16 h[8]; } ph, pl;
            #pragma unroll
            for (int u = 0; u < 8; u++) {
                float v = a[c8 * 8 + u];
                ph.h[u] = __float2bfloat16(v);
                pl.h[u] = __float2bfloat16(v - __bfloat162float(ph.h[u]));
            }
            reinterpret_cast<uint4*>(g_Ahi + so)[c8] = ph.u4;
            reinterpret_cast<uint4*>(g_Alo + so)[c8] = pl.u4;
        }
    } else {
        #pragma unroll
        for (int d = 0; d < 64; d++) a[d] = A[(size_t)(k + d) * N + g];
        #pragma unroll
        for (int d = 0; d < 64; d++) {
            #pragma unroll
            for (int r = d + 1; r < 64; r++) a[r] -= sU[r * 65 + d] * a[d];
        }
        #pragma unroll
        for (int c8 = 0; c8 < 8; c8++) {
            union { uint4 u4; __nv_bfloat16 h[8]; } ph, pl;
            #pragma unroll
            for (int u = 0; u < 8; u++) {
                float v = a[c8 * 8 + u];
                ph.h[u] = __float2bfloat16(v);
                pl.h[u] = __float2bfloat16(v - __bfloat162float(ph.h[u]));
            }
            reinterpret_cast<uint4*>(g_Bhi + so)[c8] = ph.u4;
            reinterpret_cast<uint4*>(g_Blo + so)[c8] = pl.u4;
        }
    }
}

// ---------------- HMMA trailing update + pipelined next-panel ----------------
#define SROW 72
#define SM_A_HI 0
#define SM_A_LO (128 * SROW * 2)
#define SM_B_HI (2 * 128 * SROW * 2)
#define SM_B_LO (3 * 128 * SROW * 2)
#define SM_MMA_BYTES (4 * 128 * SROW * 2)   // 73728 B >= 4160*4+64*4 for panel reuse

__global__ void __launch_bounds__(256) k_gemm_mma(int k, int s, int matBase) {
    extern __shared__ __align__(16) char smc[];
    uint32_t sb = smem_to_u32(smc);
    int mat = matBase + blockIdx.z;
    float* M = g_LU + (size_t)mat * N * N;
    size_t mo = (size_t)mat * N * 64;
    int row0 = k + 64 + blockIdx.y * 128;
    int col0 = k + 64 + blockIdx.x * 128;
    int tid = threadIdx.x;
    int lane = tid & 31, wid = tid >> 5;

    {
        int r = tid >> 1;
        int h = (tid & 1) * 4;
        int ga = min(row0 + r, N - 1);
        int gb = min(col0 + r, N - 1);
        const uint4* pAhi = reinterpret_cast<const uint4*>(g_Ahi + mo + (size_t)ga * 64);
        const uint4* pAlo = reinterpret_cast<const uint4*>(g_Alo + mo + (size_t)ga * 64);
        const uint4* pBhi = reinterpret_cast<const uint4*>(g_Bhi + mo + (size_t)gb * 64);
        const uint4* pBlo = reinterpret_cast<const uint4*>(g_Blo + mo + (size_t)gb * 64);
        #pragma unroll
        for (int c = 0; c < 4; c++) {
            int chunk = h + c;
            size_t so = (size_t)r * SROW * 2 + chunk * 16;
            *reinterpret_cast<uint4*>(smc + SM_A_HI + so) = pAhi[chunk];
            *reinterpret_cast<uint4*>(smc + SM_A_LO + so) = pAlo[chunk];
            *reinterpret_cast<uint4*>(smc + SM_B_HI + so) = pBhi[chunk];
            *reinterpret_cast<uint4*>(smc + SM_B_LO + so) = pBlo[chunk];
        }
    }
    __syncthreads();

    int wm = (wid & 3) * 32;
    int wn = (wid >> 2) * 64;

    float acc[2][8][4];
    #pragma unroll
    for (int mi = 0; mi < 2; mi++)
        #pragma unroll
        for (int ni = 0; ni < 8; ni++)
            #pragma unroll
            for (int q = 0; q < 4; q++) acc[mi][ni][q] = 0.0f;

    uint32_t aBase = sb + SM_A_HI +
        (uint32_t)(((wm + (lane & 15)) * SROW + (lane >> 4) * 8) * 2);
    uint32_t bBase = sb + SM_B_HI +
        (uint32_t)(((wn + (lane >> 4) * 8 + (lane & 7)) * SROW + ((lane >> 3) & 1) * 8) * 2);
    const uint32_t LO = (uint32_t)(128 * SROW * 2);

    #pragma unroll
    for (int ks = 0; ks < 4; ks++) {
        uint32_t ko = ks * 16 * 2;
        uint32_t a_hi[2][4], a_lo[2][4];
        uint32_t b_hi[4][4], b_lo[4][4];
        #pragma unroll
        for (int mi = 0; mi < 2; mi++) {
            uint32_t ad = aBase + (uint32_t)(mi * 16 * SROW * 2) + ko;
            ldsm_x4(a_hi[mi], ad);
            ldsm_x4(a_lo[mi], ad + LO);
        }
        #pragma unroll
        for (int np = 0; np < 4; np++) {
            uint32_t bd = bBase + (uint32_t)(np * 16 * SROW * 2) + ko;
            ldsm_x4(b_hi[np], bd);
            ldsm_x4(b_lo[np], bd + LO);
        }
        #pragma unroll
        for (int mi = 0; mi < 2; mi++) {
            #pragma unroll
            for (int ni = 0; ni < 8; ni++) {
                const uint32_t* bh = &b_hi[ni >> 1][(ni & 1) * 2];
                const uint32_t* bl = &b_lo[ni >> 1][(ni & 1) * 2];
                mma16816(acc[mi][ni], a_hi[mi], bh);
                mma16816(acc[mi][ni], a_hi[mi], bl);
                mma16816(acc[mi][ni], a_lo[mi], bh);
            }
        }
    }

    int cr = lane >> 2;
    int cc2 = (lane & 3) * 2;
    #pragma unroll
    for (int mi = 0; mi < 2; mi++) {
        #pragma unroll
        for (int ni = 0; ni < 8; ni++) {
            int cc = col0 + wn + ni * 8 + cc2;
            if (cc < N) {
                int r0 = row0 + wm + mi * 16 + cr;
                if (r0 < N) {
                    float2* p = reinterpret_cast<float2*>(&M[(size_t)r0 * N + cc]);
                    float2 v = *p;
                    v.x -= acc[mi][ni][0]; v.y -= acc[mi][ni][1];
                    *p = v;
                }
                int r1 = row0 + wm + mi * 16 + cr + 8;
                if (r1 < N) {
                    float2* p = reinterpret_cast<float2*>(&M[(size_t)r1 * N + cc]);
                    float2 v = *p;
                    v.x -= acc[mi][ni][2]; v.y -= acc[mi][ni][3];
                    *p = v;
                }
            }
        }
    }

    // ---- pipelined next-panel: tile (0,0) block factorizes panel(s+1) ----
    // The panel region (k+64..k+128)^2 lies inside this block's own C tile;
    // after __syncthreads its global writes are visible block-wide.
    if (blockIdx.x == 0 && blockIdx.y == 0) {
        __syncthreads();
        float* sU   = reinterpret_cast<float*>(smc);          // 4160 floats
        float* sRed = reinterpret_cast<float*>(smc + 4160 * 4);
        int k2 = k + 64;
        for (int t = tid; t < 64 * 64; t += 256) {
            int r = t >> 6, c = t & 63;
            sU[r * 65 + c] = M[(size_t)(k2 + r) * N + k2 + c];
        }
        __syncthreads();
        panel_fact_r4(sU, tid);
        float* P = g_panel + mat * 4224;
        for (int t = tid; t < 4160; t += 256) P[t] = sU[t];
        if (tid < 64) {
            float d = sU[tid * 65 + tid];
            P[4160 + tid] = 1.0f / d;
            sRed[tid] = logf(fabsf(d));
        }
        __syncthreads();
        if (tid == 0) {
            float sum = 0.0f;
            #pragma unroll
            for (int u = 0; u < 64; u++) sum += sRed[u];
            g_ldp[mat * 16 + s + 1] = sum;
        }
    }
}

// ---------------- output ------------------------------------------------------

__global__ void k_out(float* __restrict__ out) {
    int b = threadIdx.x;    // 32 threads
    float s0 = 0.0f;
    #pragma unroll
    for (int t = 0; t < 16; t++) s0 += g_ldp[32 * 16 + t];
    if (b < BATCH) {
        float s = 0.0f;
        #pragma unroll
        for (int t = 0; t < 16; t++) s += g_ldp[b * 16 + t];
        out[b] = g_y[b] + s - s0;
    }
}

// ---------------- launch ------------------------------------------------------

static void lu_chain(cudaStream_t str, int mb, int mc) {
    for (int s = 0; s < 15; s++) {
        int k = s * 64;
        int m2 = N - k - 64;
        int gtr = (m2 + 255) / 256;
        int gx  = (m2 + 127) / 128;
        k_trsm<<<dim3(gtr, mc, 2), 256, 0, str>>>(k, s, mb, s == 0);
        // gemm(s) also factorizes panel(s+1) and writes its logdet partial;
        // gemm(14) produces the final (16th) panel partial.
        k_gemm_mma<<<dim3(gx, gx, mc), 256, SM_MMA_BYTES, str>>>(k, s, mb);
    }
}

extern "C" void kernel_launch(void* const* d_in, const int* in_sizes, int n_in,
                              void* d_out, int out_size) {
    const int*   x  = (const int*)d_in[0];
    const float* W  = (const float*)d_in[1];
    const float* Vc = (const float*)d_in[2];
    const float* Ec = (const float*)d_in[3];
    float* out = (float*)d_out;
    (void)in_sizes; (void)n_in; (void)out_size;

    cudaFuncSetAttribute(k_gemm_mma, cudaFuncAttributeMaxDynamicSharedMemorySize, SM_MMA_BYTES);

    // prep on the default (capture) stream; k_ws first so L0 can fork early
    k_ws<<<N, 256>>>(W);
    cudaEventRecord(g_evWs, 0);
    k_vsoftmax<<<4, 256>>>(Vc);
    k_pr<<<BATCH, 1024>>>(x);
    k_sink<<<dim3(8, N - 1), 128>>>(x, Ec);
    k_fin<<<BATCH, 256>>>();
    cudaEventRecord(g_evFin, 0);

    // L0 chain forks right after k_ws (overlaps the Sinkhorn)
    cudaStreamWaitEvent(g_str[8], g_evWs, 0);
    lu_chain(g_str[8], 32, 1);
    cudaEventRecord(g_evJoin[8], g_str[8]);

    // 8 batch-matrix chains fork after k_fin
    for (int i = 0; i < 8; i++) {
        cudaStreamWaitEvent(g_str[i], g_evFin, 0);
        lu_chain(g_str[i], i * 4, 4);
        cudaEventRecord(g_evJoin[i], g_str[i]);
    }
    for (int i = 0; i < NSTREAMS; i++)
        cudaStreamWaitEvent(0, g_evJoin[i], 0);

    k_out<<<1, 32>>>(out);
}